// round 12
// baseline (speedup 1.0000x reference)
#include <cuda_runtime.h>
#include <math.h>

// ---------------- static device scratch ----------------
__device__ float g_pet[1696 * 512];
__device__ float g_x0[27787264];   // [t][b][512]
__device__ float g_x1[27787264];   // [t'][b][1024]
__device__ float g_x2[13893632];
__device__ float g_x3[6946816];
__device__ float g_xzf[55574528];  // [t][col][b]
__device__ float g_xzb[55574528];
__device__ float g_h[2][2][8192];  // [dir][parity][u*32+b]
__device__ unsigned char g_m0[54272];
__device__ unsigned char g_m1[27136];
__device__ unsigned char g_m2[13568];
__device__ unsigned char g_m3[6784];
__device__ unsigned int g_ctr[2];

// ---------------- positional encoding (fp64 like numpy) ----------------
__global__ void pet_k() {
    int i = blockIdx.x * 256 + threadIdx.x;
    if (i >= 1696 * 512) return;
    int t = i >> 9, d = i & 511;
    double expo = (double)(d & ~1) / 512.0;
    double ang = (double)t * pow(10000.0, -expo);
    g_pet[i] = (float)((d & 1) ? cos(ang) : sin(ang));
}

// ---------------- mask pyramid (dtype auto-detect) ----------------
__global__ void mask_prep(const unsigned char* __restrict__ mraw) {
    int b = blockIdx.x;  // 32 blocks
    unsigned int w0 = *(const unsigned int*)mraw;  // m[0][0] is always true
    int mode = (w0 == 1u) ? 1 : (w0 == 0x3f800000u) ? 2 : 0;  // int32 / float32 / uint8
    for (int t = threadIdx.x; t < 1696; t += 256) {
        unsigned char v;
        if (mode == 1)      v = ((const int*)mraw)[b * 1696 + t] != 0;
        else if (mode == 2) v = ((const float*)mraw)[b * 1696 + t] != 0.f;
        else                v = mraw[b * 1696 + t] != 0;
        g_m0[b * 1696 + t] = v;
    }
    __syncthreads();
    for (int t = threadIdx.x; t < 848; t += 256)
        g_m1[b * 848 + t] = g_m0[b * 1696 + 2 * t] & g_m0[b * 1696 + 2 * t + 1];
    __syncthreads();
    for (int t = threadIdx.x; t < 424; t += 256)
        g_m2[b * 424 + t] = g_m1[b * 848 + 2 * t] & g_m1[b * 848 + 2 * t + 1];
    __syncthreads();
    for (int t = threadIdx.x; t < 212; t += 256)
        g_m3[b * 212 + t] = g_m2[b * 424 + 2 * t] & g_m2[b * 424 + 2 * t + 1];
}

// ---------------- input projection + scale + PE ----------------
__global__ __launch_bounds__(256) void inproj(
    const float* __restrict__ inp, const float* __restrict__ dw,
    const float* __restrict__ db, const float* __restrict__ scale)
{
    __shared__ float si[8][40];
    const int tid = threadIdx.x;
    const int r0 = blockIdx.x * 8;  // rows r = t*32+b
    for (int e = tid; e < 320; e += 256) {
        int j = e / 40, k = e - j * 40;
        int rr = r0 + j;
        si[j][k] = inp[((size_t)(rr & 31) * 1696 + (rr >> 5)) * 40 + k];
    }
    __syncthreads();
    const float sc = (float)(sqrt(512.0 / 40.0) * 20.0) * scale[0];
    const int c = tid * 2;
    float a0[8], a1[8];
#pragma unroll
    for (int j = 0; j < 8; j++) { a0[j] = 0.f; a1[j] = 0.f; }
    for (int k = 0; k < 40; k++) {
        float w0 = dw[k * 512 + c], w1 = dw[k * 512 + c + 1];
#pragma unroll
        for (int j = 0; j < 8; j++) { a0[j] += si[j][k] * w0; a1[j] += si[j][k] * w1; }
    }
    float b0 = db[c], b1 = db[c + 1];
#pragma unroll
    for (int j = 0; j < 8; j++) {
        int rr = r0 + j, t = rr >> 5;
        g_x0[(size_t)rr * 512 + c]     = (a0[j] + b0) * sc + g_pet[t * 512 + c];
        g_x0[(size_t)rr * 512 + c + 1] = (a1[j] + b1) * sc + g_pet[t * 512 + c + 1];
    }
}

// ---------------- GEMM: out[t][col][b] = X[(t,b)][:] @ W[:][col] + bias ----------------
// X: [M rows (t*32+b)][K] row-major; W: [K][1024] row-major; N = 1024 fixed.
// BM=128, BN=128, BK=16; 256 threads; 8x8 micro-tile; epilogue staged via SMEM
// so stores to the [t][col][b] layout are 128B-coalesced (b = 32 consecutive rows).
__global__ __launch_bounds__(256, 2) void gemm_xz(
    const float* __restrict__ X, const float* __restrict__ W,
    const float* __restrict__ bias, float* __restrict__ out,
    int M, int K)
{
    __shared__ float As[16][128];
    __shared__ float Bs[16][128];
    const int bm = blockIdx.x * 128;
    const int bn = blockIdx.y * 128;
    const int tid = threadIdx.x;
    const int r0 = (tid & 15) * 8;
    const int c0 = (tid >> 4) * 8;
    float acc[8][8];
#pragma unroll
    for (int i = 0; i < 8; i++)
#pragma unroll
        for (int j = 0; j < 8; j++) acc[i][j] = 0.f;

    for (int k0 = 0; k0 < K; k0 += 16) {
#pragma unroll
        for (int j = 0; j < 2; j++) {
            int idx = tid * 2 + j;
            int row = idx >> 2, kq = (idx & 3) * 4;
            float4 v = *(const float4*)(X + (size_t)(bm + row) * K + k0 + kq);
            As[kq][row] = v.x; As[kq + 1][row] = v.y; As[kq + 2][row] = v.z; As[kq + 3][row] = v.w;
        }
#pragma unroll
        for (int j = 0; j < 2; j++) {
            int idx = tid * 2 + j;
            int kk = idx >> 5, nq = (idx & 31) * 4;
            *(float4*)(&Bs[kk][nq]) = *(const float4*)(W + (size_t)(k0 + kk) * 1024 + bn + nq);
        }
        __syncthreads();
#pragma unroll
        for (int kk = 0; kk < 16; kk++) {
            float a[8], b[8];
            *(float4*)(a)     = *(const float4*)(&As[kk][r0]);
            *(float4*)(a + 4) = *(const float4*)(&As[kk][r0 + 4]);
            *(float4*)(b)     = *(const float4*)(&Bs[kk][c0]);
            *(float4*)(b + 4) = *(const float4*)(&Bs[kk][c0 + 4]);
#pragma unroll
            for (int i = 0; i < 8; i++)
#pragma unroll
                for (int j = 0; j < 8; j++)
                    acc[i][j] += a[i] * b[j];
        }
        __syncthreads();
    }
    float bs[8];
#pragma unroll
    for (int j = 0; j < 8; j++) bs[j] = bias[bn + c0 + j];

    // Epilogue: stage 16-col chunks as [col][row] in As, then coalesced stores.
    const int gg = tid >> 4;
    const int nc_own = gg >> 1;
    const int half = (gg & 1) * 8;
    const int srow = tid & 127;
    const int scol0 = tid >> 7;
    for (int nc = 0; nc < 8; nc++) {
        __syncthreads();
        if (nc_own == nc) {
#pragma unroll
            for (int i = 0; i < 8; i++)
#pragma unroll
                for (int j = 0; j < 8; j++)
                    As[half + j][r0 + i] = acc[i][j] + bs[j];
        }
        __syncthreads();
#pragma unroll
        for (int kq = 0; kq < 8; kq++) {
            int col16 = scol0 + kq * 2;
            int grow = bm + srow;
            out[((size_t)(grow >> 5) * 1024 + bn + nc * 16 + col16) * 32 + (grow & 31)] =
                As[col16][srow];
        }
    }
}

// ---------------- persistent BiLSTM recurrence ----------------
__device__ __forceinline__ float sigf(float x) { return 1.f / (1.f + expf(-x)); }

// grid = 128 CTAs (64 fw + 64 bw), 512 threads, dyn smem 51200B.
// CTA owns 4 hidden units; warp w -> gate column (w>>2)*256 + u0 + (w&3), lane = batch.
__global__ __launch_bounds__(512, 1) void lstm_layer(
    const float* __restrict__ xzf, const float* __restrict__ xzb,
    const float* __restrict__ Wrf, const float* __restrict__ Wrb,
    const unsigned char* __restrict__ mk, int T,
    float* __restrict__ outp, int finalMode)
{
    extern __shared__ float sm[];
    float* hs  = sm;            // 8192: h[u][b]
    float* WrT = sm + 8192;     // 4096: WrT[w][u]
    float* zb  = sm + 12288;    // 512 : z[w][b]
    const int dir = blockIdx.x >> 6;
    const int u0 = (blockIdx.x & 63) * 4;
    const int tid = threadIdx.x;
    const int w = tid >> 5, lane = tid & 31;
    const int col = (w >> 2) * 256 + u0 + (w & 3);
    const float* xz = dir ? xzb : xzf;
    const float* Wr = dir ? Wrb : Wrf;

    for (int u = lane; u < 256; u += 32)
        WrT[w * 256 + u] = Wr[(size_t)u * 1024 + col];

    if (tid < 128) g_h[dir][0][u0 * 32 + tid] = 0.f;
    float creg = 0.f;
    __threadfence();
    __syncthreads();
    if (tid == 0) {  // init barrier: all 64 CTAs of this direction zeroed h
        atomicAdd(&g_ctr[dir], 1u);
        while (*(volatile unsigned int*)&g_ctr[dir] < 64u) __nanosleep(32);
        __threadfence();
    }
    __syncthreads();

    for (int s = 0; s < T; s++) {
        const int t = dir ? (T - 1 - s) : s;
        const float* hg = g_h[dir][s & 1];
#pragma unroll
        for (int i = 0; i < 4; i++) {
            int e = tid + i * 512;
            *(float4*)(&hs[e * 4]) = *(const float4*)(&hg[e * 4]);
        }
        __syncthreads();
        float acc = xz[((size_t)t * 1024 + col) * 32 + lane];
#pragma unroll 8
        for (int u = 0; u < 256; u += 4) {
            float4 wv = *(const float4*)(&WrT[w * 256 + u]);
            acc += hs[(u    ) * 32 + lane] * wv.x;
            acc += hs[(u + 1) * 32 + lane] * wv.y;
            acc += hs[(u + 2) * 32 + lane] * wv.z;
            acc += hs[(u + 3) * 32 + lane] * wv.w;
        }
        zb[w * 32 + lane] = acc;
        __syncthreads();
        if (w < 4) {  // update 4 units x 32 batches
            float zi = zb[(0  + w) * 32 + lane];
            float zf = zb[(4  + w) * 32 + lane];
            float zg = zb[(8  + w) * 32 + lane];
            float zo = zb[(12 + w) * 32 + lane];
            float cn = sigf(zf) * creg + sigf(zi) * tanhf(zg);
            float hn = sigf(zo) * tanhf(cn);
            bool m = mk[lane * T + t] != 0;
            float hp = hs[(u0 + w) * 32 + lane];
            float hv = m ? hn : hp;
            creg = m ? cn : creg;
            g_h[dir][(s + 1) & 1][(u0 + w) * 32 + lane] = hv;
            if (finalMode)
                outp[((size_t)lane * 212 + t) * 512 + dir * 256 + u0 + w] = hv;
            else  // fused concat + pyramid reshape into next layer input [t'][b][1024]
                outp[((size_t)(t >> 1) * 32 + lane) * 1024 + (t & 1) * 512 + dir * 256 + u0 + w] = hv;
            __threadfence();
        }
        __syncthreads();
        if (tid == 0) {  // per-step barrier within direction
            atomicAdd(&g_ctr[dir], 1u);
            unsigned int tgt = 64u * (unsigned int)(s + 2);
            while (*(volatile unsigned int*)&g_ctr[dir] < tgt) __nanosleep(32);
            __threadfence();
        }
        __syncthreads();
    }
}

__global__ void reset_ctr() {
    if (threadIdx.x < 2) g_ctr[threadIdx.x] = 0u;
}

__global__ void mask_out(float* outp, int extra) {
    int i = blockIdx.x * 256 + threadIdx.x;
    if (i < extra && i < 6784) outp[3473408 + i] = g_m3[i] ? 1.f : 0.f;
}

// ---------------- host ----------------
extern "C" void kernel_launch(void* const* d_in, const int* in_sizes, int n_in,
                              void* d_out, int out_size)
{
    const float *inputs = 0, *scale = 0, *dem_w = 0, *dem_b = 0;
    const void* mask = 0;
    const float *wk[8] = {0}, *wr[8] = {0}, *wb[8] = {0};
    int nk = 0, nr = 0, nb = 0;
    // Resolve by element count; within each size class the order is
    // l0_fw, l0_bw, l1_fw, l1_bw, l2_fw, l2_bw, f_fw, f_bw in any plausible metadata order.
    for (int i = 0; i < n_in; i++) {
        int s = in_sizes[i];
        const float* p = (const float*)d_in[i];
        if (s == 2170880) inputs = p;
        else if (s == 1) scale = p;
        else if (s == 20480) dem_w = p;
        else if (s == 512) dem_b = p;
        else if (s == 54272) mask = d_in[i];
        else if (s == 524288 || s == 1048576) { if (nk < 8) wk[nk++] = p; }
        else if (s == 262144) { if (nr < 8) wr[nr++] = p; }
        else if (s == 1024)   { if (nb < 8) wb[nb++] = p; }
    }

    float *x0p, *x1p, *x2p, *x3p, *xzfp, *xzbp;
    unsigned char *m0p, *m1p, *m2p, *m3p;
    cudaGetSymbolAddress((void**)&x0p,  g_x0);
    cudaGetSymbolAddress((void**)&x1p,  g_x1);
    cudaGetSymbolAddress((void**)&x2p,  g_x2);
    cudaGetSymbolAddress((void**)&x3p,  g_x3);
    cudaGetSymbolAddress((void**)&xzfp, g_xzf);
    cudaGetSymbolAddress((void**)&xzbp, g_xzb);
    cudaGetSymbolAddress((void**)&m0p,  g_m0);
    cudaGetSymbolAddress((void**)&m1p,  g_m1);
    cudaGetSymbolAddress((void**)&m2p,  g_m2);
    cudaGetSymbolAddress((void**)&m3p,  g_m3);
    cudaFuncSetAttribute(lstm_layer, cudaFuncAttributeMaxDynamicSharedMemorySize, 51200);

    pet_k<<<(1696 * 512 + 255) / 256, 256>>>();
    mask_prep<<<32, 256>>>((const unsigned char*)mask);
    inproj<<<6784, 256>>>(inputs, dem_w, dem_b, scale);

    const float* Xs[4] = {x0p, x1p, x2p, x3p};
    float* Os[4] = {x1p, x2p, x3p, (float*)d_out};
    const unsigned char* Ms[4] = {m0p, m1p, m2p, m3p};
    const int Ts[4] = {1696, 848, 424, 212};
    const int Ks[4] = {512, 1024, 1024, 1024};

    for (int L = 0; L < 4; L++) {
        int M = Ts[L] * 32;
        dim3 gg(M / 128, 8);
        gemm_xz<<<gg, 256>>>(Xs[L], wk[2 * L],     wb[2 * L],     xzfp, M, Ks[L]);
        gemm_xz<<<gg, 256>>>(Xs[L], wk[2 * L + 1], wb[2 * L + 1], xzbp, M, Ks[L]);
        reset_ctr<<<1, 32>>>();
        lstm_layer<<<128, 512, 51200>>>(xzfp, xzbp, wr[2 * L], wr[2 * L + 1],
                                        Ms[L], Ts[L], Os[L], (L == 3) ? 1 : 0);
    }

    int extra = out_size - 3473408;
    if (extra > 0) mask_out<<<(extra + 255) / 256, 256>>>((float*)d_out, extra);
}

// round 14
// speedup vs baseline: 1.1750x; 1.1750x over previous
#include <cuda_runtime.h>
#include <math.h>

typedef unsigned long long ull;

__device__ __forceinline__ ull dup2(float x) {
    ull r; asm("mov.b64 %0, {%1, %1};" : "=l"(r) : "f"(x)); return r;
}
__device__ __forceinline__ ull pack2(float a, float b) {
    ull r; asm("mov.b64 %0, {%1, %2};" : "=l"(r) : "f"(a), "f"(b)); return r;
}
__device__ __forceinline__ void ffma2(ull& d, ull a, ull b) {
    asm("fma.rn.f32x2 %0, %1, %2, %0;" : "+l"(d) : "l"(a), "l"(b));
}
__device__ __forceinline__ float2 unpk2(ull v) {
    float2 r; asm("mov.b64 {%0, %1}, %2;" : "=f"(r.x), "=f"(r.y) : "l"(v)); return r;
}

// ---------------- static device scratch ----------------
__device__ float g_pet[1696 * 512];
__device__ float g_x0[27787264];   // [t][b][512]
__device__ float g_x1[27787264];   // [t'][b][1024]
__device__ float g_x2[13893632];
__device__ float g_x3[6946816];
__device__ float g_xzf[55574528];  // [t][col][b]
__device__ float g_xzb[55574528];
__device__ float g_h[2][2][8192];  // [dir][parity][ (u4*32+b)*4 + (u&3) ]
__device__ unsigned char g_m0[54272];
__device__ unsigned char g_m1[27136];
__device__ unsigned char g_m2[13568];
__device__ unsigned char g_m3[6784];
__device__ unsigned int g_ctr[2];

// ---------------- positional encoding (fp64 like numpy) ----------------
__global__ void pet_k() {
    int i = blockIdx.x * 256 + threadIdx.x;
    if (i >= 1696 * 512) return;
    int t = i >> 9, d = i & 511;
    double expo = (double)(d & ~1) / 512.0;
    double ang = (double)t * pow(10000.0, -expo);
    g_pet[i] = (float)((d & 1) ? cos(ang) : sin(ang));
}

// ---------------- mask pyramid (dtype auto-detect) ----------------
__global__ void mask_prep(const unsigned char* __restrict__ mraw) {
    int b = blockIdx.x;  // 32 blocks
    unsigned int w0 = *(const unsigned int*)mraw;  // m[0][0] is always true
    int mode = (w0 == 1u) ? 1 : (w0 == 0x3f800000u) ? 2 : 0;  // int32 / float32 / uint8
    for (int t = threadIdx.x; t < 1696; t += 256) {
        unsigned char v;
        if (mode == 1)      v = ((const int*)mraw)[b * 1696 + t] != 0;
        else if (mode == 2) v = ((const float*)mraw)[b * 1696 + t] != 0.f;
        else                v = mraw[b * 1696 + t] != 0;
        g_m0[b * 1696 + t] = v;
    }
    __syncthreads();
    for (int t = threadIdx.x; t < 848; t += 256)
        g_m1[b * 848 + t] = g_m0[b * 1696 + 2 * t] & g_m0[b * 1696 + 2 * t + 1];
    __syncthreads();
    for (int t = threadIdx.x; t < 424; t += 256)
        g_m2[b * 424 + t] = g_m1[b * 848 + 2 * t] & g_m1[b * 848 + 2 * t + 1];
    __syncthreads();
    for (int t = threadIdx.x; t < 212; t += 256)
        g_m3[b * 212 + t] = g_m2[b * 424 + 2 * t] & g_m2[b * 424 + 2 * t + 1];
}

// ---------------- input projection + scale + PE ----------------
__global__ __launch_bounds__(256) void inproj(
    const float* __restrict__ inp, const float* __restrict__ dw,
    const float* __restrict__ db, const float* __restrict__ scale)
{
    __shared__ float si[8][40];
    const int tid = threadIdx.x;
    const int r0 = blockIdx.x * 8;  // rows r = t*32+b
    for (int e = tid; e < 320; e += 256) {
        int j = e / 40, k = e - j * 40;
        int rr = r0 + j;
        si[j][k] = inp[((size_t)(rr & 31) * 1696 + (rr >> 5)) * 40 + k];
    }
    __syncthreads();
    const float sc = (float)(sqrt(512.0 / 40.0) * 20.0) * scale[0];
    const int c = tid * 2;
    float a0[8], a1[8];
#pragma unroll
    for (int j = 0; j < 8; j++) { a0[j] = 0.f; a1[j] = 0.f; }
    for (int k = 0; k < 40; k++) {
        float w0 = dw[k * 512 + c], w1 = dw[k * 512 + c + 1];
#pragma unroll
        for (int j = 0; j < 8; j++) { a0[j] += si[j][k] * w0; a1[j] += si[j][k] * w1; }
    }
    float b0 = db[c], b1 = db[c + 1];
#pragma unroll
    for (int j = 0; j < 8; j++) {
        int rr = r0 + j, t = rr >> 5;
        g_x0[(size_t)rr * 512 + c]     = (a0[j] + b0) * sc + g_pet[t * 512 + c];
        g_x0[(size_t)rr * 512 + c + 1] = (a1[j] + b1) * sc + g_pet[t * 512 + c + 1];
    }
}

// ---------------- GEMM (FFMA2): out[t][col][b] = X @ W + bias ----------------
// X: [M rows (t*32+b)][K] row-major; W: [K][1024] row-major; N = 1024.
// BM=128, BN=128, BK=16; 256 threads; 8x8 micro-tile as 8x4 f32x2 pairs.
__global__ __launch_bounds__(256, 2) void gemm_xz(
    const float* __restrict__ X, const float* __restrict__ W,
    const float* __restrict__ bias, float* __restrict__ out,
    int M, int K)
{
    __shared__ float As[16][128];
    __shared__ float Bs[16][128];
    const int bm = blockIdx.x * 128;
    const int bn = blockIdx.y * 128;
    const int tid = threadIdx.x;
    const int r0 = (tid & 15) * 8;
    const int c0 = (tid >> 4) * 8;
    ull acc2[8][4];
#pragma unroll
    for (int i = 0; i < 8; i++)
#pragma unroll
        for (int j = 0; j < 4; j++) acc2[i][j] = 0ull;

    for (int k0 = 0; k0 < K; k0 += 16) {
#pragma unroll
        for (int j = 0; j < 2; j++) {
            int idx = tid * 2 + j;
            int row = idx >> 2, kq = (idx & 3) * 4;
            float4 v = *(const float4*)(X + (size_t)(bm + row) * K + k0 + kq);
            As[kq][row] = v.x; As[kq + 1][row] = v.y; As[kq + 2][row] = v.z; As[kq + 3][row] = v.w;
        }
#pragma unroll
        for (int j = 0; j < 2; j++) {
            int idx = tid * 2 + j;
            int kk = idx >> 5, nq = (idx & 31) * 4;
            *(float4*)(&Bs[kk][nq]) = *(const float4*)(W + (size_t)(k0 + kk) * 1024 + bn + nq);
        }
        __syncthreads();
#pragma unroll
        for (int kk = 0; kk < 16; kk++) {
            float4 a0 = *(const float4*)(&As[kk][r0]);
            float4 a1 = *(const float4*)(&As[kk][r0 + 4]);
            ulonglong2 b01 = *(const ulonglong2*)(&Bs[kk][c0]);
            ulonglong2 b23 = *(const ulonglong2*)(&Bs[kk][c0 + 4]);
            ull ad[8];
            ad[0] = dup2(a0.x); ad[1] = dup2(a0.y); ad[2] = dup2(a0.z); ad[3] = dup2(a0.w);
            ad[4] = dup2(a1.x); ad[5] = dup2(a1.y); ad[6] = dup2(a1.z); ad[7] = dup2(a1.w);
#pragma unroll
            for (int i = 0; i < 8; i++) {
                ffma2(acc2[i][0], ad[i], b01.x);
                ffma2(acc2[i][1], ad[i], b01.y);
                ffma2(acc2[i][2], ad[i], b23.x);
                ffma2(acc2[i][3], ad[i], b23.y);
            }
        }
        __syncthreads();
    }
    float acc[8][8];
#pragma unroll
    for (int i = 0; i < 8; i++)
#pragma unroll
        for (int j2 = 0; j2 < 4; j2++) {
            float2 v = unpk2(acc2[i][j2]);
            acc[i][2 * j2] = v.x; acc[i][2 * j2 + 1] = v.y;
        }
    float bs[8];
#pragma unroll
    for (int j = 0; j < 8; j++) bs[j] = bias[bn + c0 + j];

    // Epilogue: stage 16-col chunks as [col][row] in As, then coalesced stores.
    const int gg = tid >> 4;
    const int nc_own = gg >> 1;
    const int half = (gg & 1) * 8;
    const int srow = tid & 127;
    const int scol0 = tid >> 7;
    for (int nc = 0; nc < 8; nc++) {
        __syncthreads();
        if (nc_own == nc) {
#pragma unroll
            for (int i = 0; i < 8; i++)
#pragma unroll
                for (int j = 0; j < 8; j++)
                    As[half + j][r0 + i] = acc[i][j] + bs[j];
        }
        __syncthreads();
#pragma unroll
        for (int kq = 0; kq < 8; kq++) {
            int col16 = scol0 + kq * 2;
            int grow = bm + srow;
            out[((size_t)(grow >> 5) * 1024 + bn + nc * 16 + col16) * 32 + (grow & 31)] =
                As[col16][srow];
        }
    }
}

// ---------------- persistent BiLSTM recurrence (FFMA2, 128 thr) ----------------
__device__ __forceinline__ float sigf(float x) { return 1.f / (1.f + expf(-x)); }

// grid = 128 CTAs (64 fw + 64 bw), 128 threads, dyn smem 51200B.
// CTA owns 4 hidden units (u0 = cta*4). Warp w = gate w; lane = batch;
// each thread accumulates 4 gate-columns (units u0..u0+3) as 2 f32x2 pairs.
__global__ __launch_bounds__(128, 1) void lstm_layer(
    const float* __restrict__ xzf, const float* __restrict__ xzb,
    const float* __restrict__ Wrf, const float* __restrict__ Wrb,
    const unsigned char* __restrict__ mk, int T,
    float* __restrict__ outp, int finalMode)
{
    extern __shared__ float sm[];
    float* hs  = sm;            // 8192 floats: h as [u4][b][4]
    float* Wsm = sm + 8192;     // 4096 floats: [(u*4+w)*4 + j] = Wr[u][w*256+u0+j]
    float* zb  = sm + 12288;    // 512: z[gate*4+unit][b]
    const int dir = blockIdx.x >> 6;
    const int cta4 = blockIdx.x & 63;
    const int u0 = cta4 * 4;
    const int tid = threadIdx.x;
    const int w = tid >> 5, lane = tid & 31;
    const float* xz = dir ? xzb : xzf;
    const float* Wr = dir ? Wrb : Wrf;

    for (int e = tid; e < 4096; e += 128) {
        int u = e >> 4, g = (e >> 2) & 3, j = e & 3;
        Wsm[e] = Wr[(size_t)u * 1024 + g * 256 + u0 + j];
    }

    // zero this CTA's h slice; creg per (unit j = tid>>5, batch lane)
    g_h[dir][0][cta4 * 128 + lane * 4 + w] = 0.f;
    float creg = 0.f;
    __threadfence();
    __syncthreads();
    if (tid == 0) {  // init barrier: all 64 CTAs of this direction zeroed h
        atomicAdd(&g_ctr[dir], 1u);
        while (*(volatile unsigned int*)&g_ctr[dir] < 64u) __nanosleep(32);
        __threadfence();
    }
    __syncthreads();

    const ulonglong2* Wq = (const ulonglong2*)Wsm;
    const float4* H4 = (const float4*)hs;

    for (int s = 0; s < T; s++) {
        const int t = dir ? (T - 1 - s) : s;
        // xz for this thread's 4 columns (independent of h; issue early)
        const size_t xb = ((size_t)t * 1024 + w * 256 + u0) * 32 + lane;
        float x0 = xz[xb], x1 = xz[xb + 32], x2 = xz[xb + 64], x3 = xz[xb + 96];
        ull acc0 = pack2(x0, x1);
        ull acc1 = pack2(x2, x3);

        // stage h (8192 floats = 32KB) via cp.async
        {
            const char* src = (const char*)g_h[dir][s & 1] + tid * 16;
            unsigned int dst = (unsigned int)__cvta_generic_to_shared(hs) + tid * 16;
#pragma unroll
            for (int i = 0; i < 16; i++)
                asm volatile("cp.async.cg.shared.global [%0], [%1], 16;"
                             :: "r"(dst + i * 2048), "l"(src + i * 2048));
            asm volatile("cp.async.commit_group;");
            asm volatile("cp.async.wait_group 0;" ::: "memory");
        }
        __syncthreads();

#pragma unroll 4
        for (int u4 = 0; u4 < 64; u4++) {
            float4 h4 = H4[u4 * 32 + lane];
            ulonglong2 w0 = Wq[(u4 * 4 + 0) * 4 + w];
            ulonglong2 w1 = Wq[(u4 * 4 + 1) * 4 + w];
            ulonglong2 w2 = Wq[(u4 * 4 + 2) * 4 + w];
            ulonglong2 w3 = Wq[(u4 * 4 + 3) * 4 + w];
            ull hd;
            hd = dup2(h4.x); ffma2(acc0, hd, w0.x); ffma2(acc1, hd, w0.y);
            hd = dup2(h4.y); ffma2(acc0, hd, w1.x); ffma2(acc1, hd, w1.y);
            hd = dup2(h4.z); ffma2(acc0, hd, w2.x); ffma2(acc1, hd, w2.y);
            hd = dup2(h4.w); ffma2(acc0, hd, w3.x); ffma2(acc1, hd, w3.y);
        }
        float2 z01 = unpk2(acc0), z23 = unpk2(acc1);
        zb[(w * 4 + 0) * 32 + lane] = z01.x;
        zb[(w * 4 + 1) * 32 + lane] = z01.y;
        zb[(w * 4 + 2) * 32 + lane] = z23.x;
        zb[(w * 4 + 3) * 32 + lane] = z23.y;
        __syncthreads();

        {   // gate update: thread = (unit j = w, batch = lane)
            const int j = w;
            float zi = zb[(0  + j) * 32 + lane];
            float zf = zb[(4  + j) * 32 + lane];
            float zg = zb[(8  + j) * 32 + lane];
            float zo = zb[(12 + j) * 32 + lane];
            float cn = sigf(zf) * creg + sigf(zi) * tanhf(zg);
            float hn = sigf(zo) * tanhf(cn);
            bool m = mk[lane * T + t] != 0;
            float hp = hs[(cta4 * 32 + lane) * 4 + j];
            float hv = m ? hn : hp;
            creg = m ? cn : creg;
            g_h[dir][(s + 1) & 1][cta4 * 128 + lane * 4 + j] = hv;
            if (finalMode)
                outp[((size_t)lane * 212 + t) * 512 + dir * 256 + u0 + j] = hv;
            else  // fused concat + pyramid reshape into next layer input [t'][b][1024]
                outp[((size_t)(t >> 1) * 32 + lane) * 1024 + (t & 1) * 512 + dir * 256 + u0 + j] = hv;
            __threadfence();
        }
        __syncthreads();
        if (tid == 0) {  // per-step barrier within direction
            atomicAdd(&g_ctr[dir], 1u);
            unsigned int tgt = 64u * (unsigned int)(s + 2);
            while (*(volatile unsigned int*)&g_ctr[dir] < tgt) __nanosleep(32);
            __threadfence();
        }
        __syncthreads();
    }
}

__global__ void reset_ctr() {
    if (threadIdx.x < 2) g_ctr[threadIdx.x] = 0u;
}

__global__ void mask_out(float* outp, int extra) {
    int i = blockIdx.x * 256 + threadIdx.x;
    if (i < extra && i < 6784) outp[3473408 + i] = g_m3[i] ? 1.f : 0.f;
}

// ---------------- host ----------------
extern "C" void kernel_launch(void* const* d_in, const int* in_sizes, int n_in,
                              void* d_out, int out_size)
{
    const float *inputs = 0, *scale = 0, *dem_w = 0, *dem_b = 0;
    const void* mask = 0;
    const float *wk[8] = {0}, *wr[8] = {0}, *wb[8] = {0};
    int nk = 0, nr = 0, nb = 0;
    for (int i = 0; i < n_in; i++) {
        int s = in_sizes[i];
        const float* p = (const float*)d_in[i];
        if (s == 2170880) inputs = p;
        else if (s == 1) scale = p;
        else if (s == 20480) dem_w = p;
        else if (s == 512) dem_b = p;
        else if (s == 54272) mask = d_in[i];
        else if (s == 524288 || s == 1048576) { if (nk < 8) wk[nk++] = p; }
        else if (s == 262144) { if (nr < 8) wr[nr++] = p; }
        else if (s == 1024)   { if (nb < 8) wb[nb++] = p; }
    }

    float *x0p, *x1p, *x2p, *x3p, *xzfp, *xzbp;
    unsigned char *m0p, *m1p, *m2p, *m3p;
    cudaGetSymbolAddress((void**)&x0p,  g_x0);
    cudaGetSymbolAddress((void**)&x1p,  g_x1);
    cudaGetSymbolAddress((void**)&x2p,  g_x2);
    cudaGetSymbolAddress((void**)&x3p,  g_x3);
    cudaGetSymbolAddress((void**)&xzfp, g_xzf);
    cudaGetSymbolAddress((void**)&xzbp, g_xzb);
    cudaGetSymbolAddress((void**)&m0p,  g_m0);
    cudaGetSymbolAddress((void**)&m1p,  g_m1);
    cudaGetSymbolAddress((void**)&m2p,  g_m2);
    cudaGetSymbolAddress((void**)&m3p,  g_m3);
    cudaFuncSetAttribute(lstm_layer, cudaFuncAttributeMaxDynamicSharedMemorySize, 51200);

    pet_k<<<(1696 * 512 + 255) / 256, 256>>>();
    mask_prep<<<32, 256>>>((const unsigned char*)mask);
    inproj<<<6784, 256>>>(inputs, dem_w, dem_b, scale);

    const float* Xs[4] = {x0p, x1p, x2p, x3p};
    float* Os[4] = {x1p, x2p, x3p, (float*)d_out};
    const unsigned char* Ms[4] = {m0p, m1p, m2p, m3p};
    const int Ts[4] = {1696, 848, 424, 212};
    const int Ks[4] = {512, 1024, 1024, 1024};

    for (int L = 0; L < 4; L++) {
        int M = Ts[L] * 32;
        dim3 gg(M / 128, 8);
        gemm_xz<<<gg, 256>>>(Xs[L], wk[2 * L],     wb[2 * L],     xzfp, M, Ks[L]);
        gemm_xz<<<gg, 256>>>(Xs[L], wk[2 * L + 1], wb[2 * L + 1], xzbp, M, Ks[L]);
        reset_ctr<<<1, 32>>>();
        lstm_layer<<<128, 128, 51200>>>(xzfp, xzbp, wr[2 * L], wr[2 * L + 1],
                                        Ms[L], Ts[L], Os[L], (L == 3) ? 1 : 0);
    }

    int extra = out_size - 3473408;
    if (extra > 0) mask_out<<<(extra + 255) / 256, 256>>>((float*)d_out, extra);
}

// round 16
// speedup vs baseline: 1.4636x; 1.2456x over previous
#include <cuda_runtime.h>
#include <cuda_bf16.h>
#include <math.h>
#include <stdint.h>

typedef unsigned long long ull;
typedef __nv_bfloat16 bf16;

// ======================= small PTX helpers =======================
__device__ __forceinline__ ull dup2(float x) {
    ull r; asm("mov.b64 %0, {%1, %1};" : "=l"(r) : "f"(x)); return r;
}
__device__ __forceinline__ ull pack2(float a, float b) {
    ull r; asm("mov.b64 %0, {%1, %2};" : "=l"(r) : "f"(a), "f"(b)); return r;
}
__device__ __forceinline__ void ffma2(ull& d, ull a, ull b) {
    asm("fma.rn.f32x2 %0, %1, %2, %0;" : "+l"(d) : "l"(a), "l"(b));
}
__device__ __forceinline__ float2 unpk2(ull v) {
    float2 r; asm("mov.b64 {%0, %1}, %2;" : "=f"(r.x), "=f"(r.y) : "l"(v)); return r;
}
__device__ __forceinline__ uint32_t s2u(const void* p) {
    uint32_t a;
    asm("{ .reg .u64 t; cvta.to.shared.u64 t, %1; cvt.u32.u64 %0, t; }" : "=r"(a) : "l"(p));
    return a;
}
__device__ __forceinline__ void cp16(uint32_t dst, const void* src) {
    asm volatile("cp.async.cg.shared.global [%0], [%1], 16;" :: "r"(dst), "l"(src));
}
__device__ __forceinline__ void cp_commit() { asm volatile("cp.async.commit_group;"); }
__device__ __forceinline__ void cp_wait0()  { asm volatile("cp.async.wait_group 0;" ::: "memory"); }
__device__ __forceinline__ void cp_wait1()  { asm volatile("cp.async.wait_group 1;" ::: "memory"); }

__device__ __forceinline__ void ldsm4(uint32_t* r, uint32_t a) {
    asm volatile("ldmatrix.sync.aligned.m8n8.x4.shared.b16 {%0,%1,%2,%3}, [%4];"
                 : "=r"(r[0]), "=r"(r[1]), "=r"(r[2]), "=r"(r[3]) : "r"(a));
}
__device__ __forceinline__ void mma16816(float* d, const uint32_t* a, const uint32_t* b) {
    asm volatile(
        "mma.sync.aligned.m16n8k16.row.col.f32.bf16.bf16.f32 "
        "{%0,%1,%2,%3}, {%4,%5,%6,%7}, {%8,%9}, {%0,%1,%2,%3};"
        : "+f"(d[0]), "+f"(d[1]), "+f"(d[2]), "+f"(d[3])
        : "r"(a[0]), "r"(a[1]), "r"(a[2]), "r"(a[3]), "r"(b[0]), "r"(b[1]));
}

// swizzled byte offset within a 128-row x 32-bf16 (8KB) tile; conflict-free ldmatrix
__device__ __forceinline__ uint32_t tswz(int r, int c) {
    int line = r >> 1;
    int ch = ((r & 1) * 4 + c) ^ (line & 7);
    return (uint32_t)(line * 128 + ch * 16);
}

// ======================= static device scratch =======================
__device__ float g_pet[1696 * 512];
__device__ bf16 g_xh0[27787264], g_xl0[27787264];   // [t*32+b][512]
__device__ bf16 g_xh1[27787264], g_xl1[27787264];   // [t'*32+b][1024]
__device__ bf16 g_xh2[13893632], g_xl2[13893632];
__device__ bf16 g_xh3[6946816],  g_xl3[6946816];
__device__ bf16 g_wth[7340032], g_wtl[7340032];     // transposed weights [n][k]
__device__ float g_xzf[55574528];  // [t][col][b]
__device__ float g_xzb[55574528];
__device__ float g_h[2][2][8192];
__device__ unsigned char g_m0[54272];
__device__ unsigned char g_m1[27136];
__device__ unsigned char g_m2[13568];
__device__ unsigned char g_m3[6784];
__device__ unsigned int g_ctr[2];

// ======================= positional encoding =======================
__global__ void pet_k() {
    int i = blockIdx.x * 256 + threadIdx.x;
    if (i >= 1696 * 512) return;
    int t = i >> 9, d = i & 511;
    double expo = (double)(d & ~1) / 512.0;
    double ang = (double)t * pow(10000.0, -expo);
    g_pet[i] = (float)((d & 1) ? cos(ang) : sin(ang));
}

// ======================= mask pyramid =======================
__global__ void mask_prep(const unsigned char* __restrict__ mraw) {
    int b = blockIdx.x;
    unsigned int w0 = *(const unsigned int*)mraw;
    int mode = (w0 == 1u) ? 1 : (w0 == 0x3f800000u) ? 2 : 0;
    for (int t = threadIdx.x; t < 1696; t += 256) {
        unsigned char v;
        if (mode == 1)      v = ((const int*)mraw)[b * 1696 + t] != 0;
        else if (mode == 2) v = ((const float*)mraw)[b * 1696 + t] != 0.f;
        else                v = mraw[b * 1696 + t] != 0;
        g_m0[b * 1696 + t] = v;
    }
    __syncthreads();
    for (int t = threadIdx.x; t < 848; t += 256)
        g_m1[b * 848 + t] = g_m0[b * 1696 + 2 * t] & g_m0[b * 1696 + 2 * t + 1];
    __syncthreads();
    for (int t = threadIdx.x; t < 424; t += 256)
        g_m2[b * 424 + t] = g_m1[b * 848 + 2 * t] & g_m1[b * 848 + 2 * t + 1];
    __syncthreads();
    for (int t = threadIdx.x; t < 212; t += 256)
        g_m3[b * 212 + t] = g_m2[b * 424 + 2 * t] & g_m2[b * 424 + 2 * t + 1];
}

// ======================= input projection -> bf16 split =======================
__global__ __launch_bounds__(256) void inproj(
    const float* __restrict__ inp, const float* __restrict__ dw,
    const float* __restrict__ db, const float* __restrict__ scale)
{
    __shared__ float si[8][40];
    const int tid = threadIdx.x;
    const int r0 = blockIdx.x * 8;
    for (int e = tid; e < 320; e += 256) {
        int j = e / 40, k = e - j * 40;
        int rr = r0 + j;
        si[j][k] = inp[((size_t)(rr & 31) * 1696 + (rr >> 5)) * 40 + k];
    }
    __syncthreads();
    const float sc = (float)(sqrt(512.0 / 40.0) * 20.0) * scale[0];
    const int c = tid * 2;
    float a0[8], a1[8];
#pragma unroll
    for (int j = 0; j < 8; j++) { a0[j] = 0.f; a1[j] = 0.f; }
    for (int k = 0; k < 40; k++) {
        float w0 = dw[k * 512 + c], w1 = dw[k * 512 + c + 1];
#pragma unroll
        for (int j = 0; j < 8; j++) { a0[j] += si[j][k] * w0; a1[j] += si[j][k] * w1; }
    }
    float b0 = db[c], b1 = db[c + 1];
#pragma unroll
    for (int j = 0; j < 8; j++) {
        int rr = r0 + j, t = rr >> 5;
        float v0 = (a0[j] + b0) * sc + g_pet[t * 512 + c];
        float v1 = (a1[j] + b1) * sc + g_pet[t * 512 + c + 1];
        bf16 h0 = __float2bfloat16(v0);
        bf16 h1 = __float2bfloat16(v1);
        size_t o = (size_t)rr * 512 + c;
        g_xh0[o] = h0;     g_xl0[o]     = __float2bfloat16(v0 - __bfloat162float(h0));
        g_xh0[o + 1] = h1; g_xl0[o + 1] = __float2bfloat16(v1 - __bfloat162float(h1));
    }
}

// ======================= weight transpose + bf16 split =======================
// W: [K][1024] fp32 -> th/tl: [1024][K] bf16
__global__ void conv_w(const float* __restrict__ W, bf16* __restrict__ th,
                       bf16* __restrict__ tl, int K) {
    __shared__ float tile[32][33];
    int k0 = blockIdx.x * 32, n0 = blockIdx.y * 32;
    int tx = threadIdx.x, ty = threadIdx.y;
    for (int i = ty; i < 32; i += 8)
        tile[i][tx] = W[(size_t)(k0 + i) * 1024 + n0 + tx];
    __syncthreads();
    for (int i = ty; i < 32; i += 8) {
        float v = tile[tx][i];  // W[k0+tx][n0+i]
        bf16 h = __float2bfloat16(v);
        size_t o = (size_t)(n0 + i) * K + k0 + tx;
        th[o] = h;
        tl[o] = __float2bfloat16(v - __bfloat162float(h));
    }
}

// ======================= split-bf16 GEMM via mma.sync (HMMA) =======================
// out[t][col][b] = X @ W + bias, fp32-accurate via AhBh + AlBh + AhBl.
// A: [M][K] bf16 hi/lo. B: [1024][K] bf16 hi/lo (pre-transposed).
// BM=128, BN=128, BK=32. 256 threads = 8 warps (4m x 2n), warp tile 32x64.
// Double-buffered cp.async SMEM: 4 sub-tiles (Ah,Al,Bh,Bl) of 8KB -> 32KB/buf.
#define GM_BUF 32768
#define GM_SMEM (2 * GM_BUF)

__global__ __launch_bounds__(256, 1) void gemm_mma(
    const bf16* __restrict__ Ah, const bf16* __restrict__ Al,
    const bf16* __restrict__ Bh, const bf16* __restrict__ Bl,
    const float* __restrict__ bias, float* __restrict__ out,
    int M, int K)
{
    extern __shared__ __align__(128) char smem[];
    const uint32_t sb = s2u(smem);
    const int tid = threadIdx.x;
    const int wid = tid >> 5, lane = tid & 31;
    const int wm = wid >> 1, wn = wid & 1;
    const int bm = blockIdx.x * 128, bn = blockIdx.y * 128;
    const int nk = K >> 5;

    // ldmatrix offsets (within an 8KB sub-tile)
    uint32_t offA[2][2], offB[4][2];
#pragma unroll
    for (int mt = 0; mt < 2; mt++)
#pragma unroll
        for (int kh = 0; kh < 2; kh++)
            offA[mt][kh] = tswz(wm * 32 + mt * 16 + (lane & 15), kh * 2 + (lane >> 4));
#pragma unroll
    for (int g = 0; g < 4; g++)
#pragma unroll
        for (int kh = 0; kh < 2; kh++)
            offB[g][kh] = tswz(wn * 64 + (2 * g + ((lane >> 4) & 1)) * 8 + (lane & 7),
                               kh * 2 + ((lane >> 3) & 1));

    float acc[2][8][4];
#pragma unroll
    for (int i = 0; i < 2; i++)
#pragma unroll
        for (int j = 0; j < 8; j++)
#pragma unroll
            for (int q = 0; q < 4; q++) acc[i][j][q] = 0.f;

    // stage k-tile kt into buffer
    const int sr = tid >> 2, sc = tid & 3;            // idx = tid
    const int sr2 = (tid + 256) >> 2, sc2 = (tid + 256) & 3;
    const uint32_t d1 = tswz(sr, sc), d2 = tswz(sr2, sc2);
#define STAGE(kt, base) do {                                                     \
    int ko = (kt) * 32;                                                          \
    const bf16* arow1 = Ah + (size_t)(bm + sr) * K + ko + sc * 8;                \
    const bf16* arow2 = Ah + (size_t)(bm + sr2) * K + ko + sc2 * 8;              \
    const bf16* brow1 = Bh + (size_t)(bn + sr) * K + ko + sc * 8;                \
    const bf16* brow2 = Bh + (size_t)(bn + sr2) * K + ko + sc2 * 8;              \
    const bf16* crow1 = Al + (size_t)(bm + sr) * K + ko + sc * 8;                \
    const bf16* crow2 = Al + (size_t)(bm + sr2) * K + ko + sc2 * 8;              \
    const bf16* drow1 = Bl + (size_t)(bn + sr) * K + ko + sc * 8;                \
    const bf16* drow2 = Bl + (size_t)(bn + sr2) * K + ko + sc2 * 8;              \
    cp16((base) + d1,          arow1); cp16((base) + d2,          arow2);        \
    cp16((base) + 8192 + d1,   crow1); cp16((base) + 8192 + d2,   crow2);        \
    cp16((base) + 16384 + d1,  brow1); cp16((base) + 16384 + d2,  brow2);        \
    cp16((base) + 24576 + d1,  drow1); cp16((base) + 24576 + d2,  drow2);        \
    cp_commit();                                                                 \
} while (0)

    STAGE(0, sb);
    for (int kt = 0; kt < nk; kt++) {
        const uint32_t cbase = sb + (uint32_t)(kt & 1) * GM_BUF;
        if (kt + 1 < nk) {
            STAGE(kt + 1, sb + (uint32_t)((kt + 1) & 1) * GM_BUF);
            cp_wait1();
        } else {
            cp_wait0();
        }
        __syncthreads();
#pragma unroll
        for (int kh = 0; kh < 2; kh++) {
            uint32_t ah[2][4], al[2][4], bh[4][4], bl[4][4];
#pragma unroll
            for (int mt = 0; mt < 2; mt++) {
                ldsm4(ah[mt], cbase + offA[mt][kh]);
                ldsm4(al[mt], cbase + 8192 + offA[mt][kh]);
            }
#pragma unroll
            for (int g = 0; g < 4; g++) {
                ldsm4(bh[g], cbase + 16384 + offB[g][kh]);
                ldsm4(bl[g], cbase + 24576 + offB[g][kh]);
            }
#pragma unroll
            for (int mt = 0; mt < 2; mt++)
#pragma unroll
                for (int nt = 0; nt < 8; nt++) {
                    const uint32_t* bph = bh[nt >> 1] + (nt & 1) * 2;
                    const uint32_t* bpl = bl[nt >> 1] + (nt & 1) * 2;
                    mma16816(acc[mt][nt], ah[mt], bph);
                    mma16816(acc[mt][nt], al[mt], bph);
                    mma16816(acc[mt][nt], ah[mt], bpl);
                }
        }
        __syncthreads();
    }

    // epilogue: D[row][col] -> out[(row>>5)*1024 + col][row&31], + bias
    const int r_base = bm + wm * 32 + (lane >> 2);
    const int c_base = bn + wn * 64 + (lane & 3) * 2;
#pragma unroll
    for (int mt = 0; mt < 2; mt++)
#pragma unroll
        for (int nt = 0; nt < 8; nt++) {
            int row = r_base + mt * 16;
            int col = c_base + nt * 8;
            float b0 = __ldg(bias + col), b1 = __ldg(bias + col + 1);
            size_t o0 = ((size_t)(row >> 5) * 1024 + col) * 32 + (row & 31);
            out[o0]      = acc[mt][nt][0] + b0;
            out[o0 + 32] = acc[mt][nt][1] + b1;
            int row2 = row + 8;
            size_t o1 = ((size_t)(row2 >> 5) * 1024 + col) * 32 + (row2 & 31);
            out[o1]      = acc[mt][nt][2] + b0;
            out[o1 + 32] = acc[mt][nt][3] + b1;
        }
}

// ======================= persistent BiLSTM recurrence =======================
__device__ __forceinline__ float sigf(float x) { return 1.f / (1.f + expf(-x)); }

__global__ __launch_bounds__(128, 1) void lstm_layer(
    const float* __restrict__ xzf, const float* __restrict__ xzb,
    const float* __restrict__ Wrf, const float* __restrict__ Wrb,
    const unsigned char* __restrict__ mk, int T,
    float* __restrict__ outf, bf16* __restrict__ outh, bf16* __restrict__ outl,
    int finalMode)
{
    extern __shared__ float sm[];
    float* hs  = sm;            // 8192 floats: h as [u4][b][4]
    float* Wsm = sm + 8192;     // 4096 floats
    float* zb  = sm + 12288;    // 512
    const int dir = blockIdx.x >> 6;
    const int cta4 = blockIdx.x & 63;
    const int u0 = cta4 * 4;
    const int tid = threadIdx.x;
    const int w = tid >> 5, lane = tid & 31;
    const float* xz = dir ? xzb : xzf;
    const float* Wr = dir ? Wrb : Wrf;

    for (int e = tid; e < 4096; e += 128) {
        int u = e >> 4, g = (e >> 2) & 3, j = e & 3;
        Wsm[e] = Wr[(size_t)u * 1024 + g * 256 + u0 + j];
    }

    g_h[dir][0][cta4 * 128 + lane * 4 + w] = 0.f;
    float creg = 0.f;
    __threadfence();
    __syncthreads();
    if (tid == 0) {
        atomicAdd(&g_ctr[dir], 1u);
        while (*(volatile unsigned int*)&g_ctr[dir] < 64u) __nanosleep(32);
        __threadfence();
    }
    __syncthreads();

    const ulonglong2* Wq = (const ulonglong2*)Wsm;
    const float4* H4 = (const float4*)hs;

    for (int s = 0; s < T; s++) {
        const int t = dir ? (T - 1 - s) : s;
        const size_t xb = ((size_t)t * 1024 + w * 256 + u0) * 32 + lane;
        float x0 = xz[xb], x1 = xz[xb + 32], x2 = xz[xb + 64], x3 = xz[xb + 96];
        ull acc0 = pack2(x0, x1);
        ull acc1 = pack2(x2, x3);

        {   // stage h (32KB) via cp.async
            const char* src = (const char*)g_h[dir][s & 1] + tid * 16;
            unsigned int dst = s2u(hs) + tid * 16;
#pragma unroll
            for (int i = 0; i < 16; i++)
                cp16(dst + i * 2048, src + i * 2048);
            cp_commit();
            cp_wait0();
        }
        __syncthreads();

#pragma unroll 4
        for (int u4 = 0; u4 < 64; u4++) {
            float4 h4 = H4[u4 * 32 + lane];
            ulonglong2 w0 = Wq[(u4 * 4 + 0) * 4 + w];
            ulonglong2 w1 = Wq[(u4 * 4 + 1) * 4 + w];
            ulonglong2 w2 = Wq[(u4 * 4 + 2) * 4 + w];
            ulonglong2 w3 = Wq[(u4 * 4 + 3) * 4 + w];
            ull hd;
            hd = dup2(h4.x); ffma2(acc0, hd, w0.x); ffma2(acc1, hd, w0.y);
            hd = dup2(h4.y); ffma2(acc0, hd, w1.x); ffma2(acc1, hd, w1.y);
            hd = dup2(h4.z); ffma2(acc0, hd, w2.x); ffma2(acc1, hd, w2.y);
            hd = dup2(h4.w); ffma2(acc0, hd, w3.x); ffma2(acc1, hd, w3.y);
        }
        float2 z01 = unpk2(acc0), z23 = unpk2(acc1);
        zb[(w * 4 + 0) * 32 + lane] = z01.x;
        zb[(w * 4 + 1) * 32 + lane] = z01.y;
        zb[(w * 4 + 2) * 32 + lane] = z23.x;
        zb[(w * 4 + 3) * 32 + lane] = z23.y;
        __syncthreads();

        {   // gate update: thread = (unit j = w, batch = lane)
            const int j = w;
            float zi = zb[(0  + j) * 32 + lane];
            float zf = zb[(4  + j) * 32 + lane];
            float zg = zb[(8  + j) * 32 + lane];
            float zo = zb[(12 + j) * 32 + lane];
            float cn = sigf(zf) * creg + sigf(zi) * tanhf(zg);
            float hn = sigf(zo) * tanhf(cn);
            bool m = mk[lane * T + t] != 0;
            float hp = hs[(cta4 * 32 + lane) * 4 + j];
            float hv = m ? hn : hp;
            creg = m ? cn : creg;
            g_h[dir][(s + 1) & 1][cta4 * 128 + lane * 4 + j] = hv;
            if (finalMode) {
                outf[((size_t)lane * 212 + t) * 512 + dir * 256 + u0 + j] = hv;
            } else {
                size_t o = ((size_t)(t >> 1) * 32 + lane) * 1024 + (t & 1) * 512 + dir * 256 + u0 + j;
                bf16 hh = __float2bfloat16(hv);
                outh[o] = hh;
                outl[o] = __float2bfloat16(hv - __bfloat162float(hh));
            }
            __threadfence();
        }
        __syncthreads();
        if (tid == 0) {
            atomicAdd(&g_ctr[dir], 1u);
            unsigned int tgt = 64u * (unsigned int)(s + 2);
            while (*(volatile unsigned int*)&g_ctr[dir] < tgt) __nanosleep(32);
            __threadfence();
        }
        __syncthreads();
    }
}

__global__ void reset_ctr() {
    if (threadIdx.x < 2) g_ctr[threadIdx.x] = 0u;
}

__global__ void mask_out(float* outp, int extra) {
    int i = blockIdx.x * 256 + threadIdx.x;
    if (i < extra && i < 6784) outp[3473408 + i] = g_m3[i] ? 1.f : 0.f;
}

// ======================= host =======================
extern "C" void kernel_launch(void* const* d_in, const int* in_sizes, int n_in,
                              void* d_out, int out_size)
{
    const float *inputs = 0, *scale = 0, *dem_w = 0, *dem_b = 0;
    const void* mask = 0;
    const float *wk[8] = {0}, *wr[8] = {0}, *wb[8] = {0};
    int nk = 0, nr = 0, nb = 0;
    for (int i = 0; i < n_in; i++) {
        int s = in_sizes[i];
        const float* p = (const float*)d_in[i];
        if (s == 2170880) inputs = p;
        else if (s == 1) scale = p;
        else if (s == 20480) dem_w = p;
        else if (s == 512) dem_b = p;
        else if (s == 54272) mask = d_in[i];
        else if (s == 524288 || s == 1048576) { if (nk < 8) wk[nk++] = p; }
        else if (s == 262144) { if (nr < 8) wr[nr++] = p; }
        else if (s == 1024)   { if (nb < 8) wb[nb++] = p; }
    }

    bf16 *xh[4], *xl[4], *wthp, *wtlp;
    float *xzfp, *xzbp;
    unsigned char *m0p, *m1p, *m2p, *m3p;
    cudaGetSymbolAddress((void**)&xh[0], g_xh0); cudaGetSymbolAddress((void**)&xl[0], g_xl0);
    cudaGetSymbolAddress((void**)&xh[1], g_xh1); cudaGetSymbolAddress((void**)&xl[1], g_xl1);
    cudaGetSymbolAddress((void**)&xh[2], g_xh2); cudaGetSymbolAddress((void**)&xl[2], g_xl2);
    cudaGetSymbolAddress((void**)&xh[3], g_xh3); cudaGetSymbolAddress((void**)&xl[3], g_xl3);
    cudaGetSymbolAddress((void**)&wthp, g_wth);  cudaGetSymbolAddress((void**)&wtlp, g_wtl);
    cudaGetSymbolAddress((void**)&xzfp, g_xzf);  cudaGetSymbolAddress((void**)&xzbp, g_xzb);
    cudaGetSymbolAddress((void**)&m0p, g_m0);    cudaGetSymbolAddress((void**)&m1p, g_m1);
    cudaGetSymbolAddress((void**)&m2p, g_m2);    cudaGetSymbolAddress((void**)&m3p, g_m3);

    cudaFuncSetAttribute(lstm_layer, cudaFuncAttributeMaxDynamicSharedMemorySize, 51200);
    cudaFuncSetAttribute(gemm_mma,   cudaFuncAttributeMaxDynamicSharedMemorySize, GM_SMEM);

    pet_k<<<(1696 * 512 + 255) / 256, 256>>>();
    mask_prep<<<32, 256>>>((const unsigned char*)mask);
    inproj<<<6784, 256>>>(inputs, dem_w, dem_b, scale);

    static const size_t woff[8] = {0, 524288, 1048576, 2097152, 3145728, 4194304, 5242880, 6291456};
    static const int wkk[8] = {512, 512, 1024, 1024, 1024, 1024, 1024, 1024};
    for (int m = 0; m < 8; m++) {
        dim3 g(wkk[m] / 32, 32);
        conv_w<<<g, dim3(32, 8)>>>(wk[m], wthp + woff[m], wtlp + woff[m], wkk[m]);
    }

    const unsigned char* Ms[4] = {m0p, m1p, m2p, m3p};
    const int Ts[4] = {1696, 848, 424, 212};
    const int Ks[4] = {512, 1024, 1024, 1024};

    for (int L = 0; L < 4; L++) {
        int M = Ts[L] * 32;
        dim3 gg(M / 128, 8);
        gemm_mma<<<gg, 256, GM_SMEM>>>(xh[L], xl[L], wthp + woff[2 * L], wtlp + woff[2 * L],
                                       wb[2 * L], xzfp, M, Ks[L]);
        gemm_mma<<<gg, 256, GM_SMEM>>>(xh[L], xl[L], wthp + woff[2 * L + 1], wtlp + woff[2 * L + 1],
                                       wb[2 * L + 1], xzbp, M, Ks[L]);
        reset_ctr<<<1, 32>>>();
        int fin = (L == 3) ? 1 : 0;
        lstm_layer<<<128, 128, 51200>>>(xzfp, xzbp, wr[2 * L], wr[2 * L + 1], Ms[L],
                                        Ts[L], (float*)d_out,
                                        fin ? (bf16*)0 : xh[L + 1],
                                        fin ? (bf16*)0 : xl[L + 1], fin);
    }

    int extra = out_size - 3473408;
    if (extra > 0) mask_out<<<(extra + 255) / 256, 256>>>((float*)d_out, extra);
}